// round 11
// baseline (speedup 1.0000x reference)
#include <cuda_runtime.h>
#include <cuda_bf16.h>
#include <mma.h>
#include <math.h>
#include <stdint.h>

using namespace nvcuda;

// ---------------------------------------------------------------------------
// R-NEM cell on tensor cores (wmma bf16 HMMA; tcgen05 unavailable on the
// harness's compute_103 PTX target). fp32 emulated as bf16 hi/lo 3-term.
// R10: BM=128/NT=256/K-chunk=64 (R8 geometry) with 512 threads in ONE CTA:
//      64 acc regs/thread (no 255-reg cap), 4 warps/SMSP, single B copy.
//      R9 showed occupancy alone isn't the lever; R8 showed the reg cap.
// ---------------------------------------------------------------------------

#define EPS_LN 1e-5f

static constexpr int Bn  = 2048;
static constexpr int Kn  = 8;
static constexpr int BK  = Bn * Kn;          // 16384 entity rows
static constexpr int RR  = BK * (Kn - 1);    // 114688 pair rows
static constexpr int H1  = 250;
static constexpr int Mx  = 576;

// fp32 scratch
__device__ float g_F  [BK * 256];
__device__ float g_G  [BK * 256];
__device__ float g_ctx[RR * H1];
__device__ float g_att[RR];
__device__ float g_zeros[256];               // zero bias for F/G GEMMs

// bf16 hi/lo activations (k-padded, zero-filled pad)
__device__ __nv_bfloat16 g_sta_h[BK * 256], g_sta_l[BK * 256];
__device__ __nv_bfloat16 g_x_h  [BK * 576], g_x_l  [BK * 576];
__device__ __nv_bfloat16 g_s1_h [BK * 256], g_s1_l [BK * 256];
__device__ __nv_bfloat16 g_co_h [RR * 256], g_co_l [RR * 256];
__device__ __nv_bfloat16 g_ef_h [BK * 256], g_ef_l [BK * 256];

// Pre-split weights, [Kpad][NT] row-major; 250-wide K segments padded to 256.
__device__ __nv_bfloat16 g_enc_h [256 * 256],  g_enc_l [256 * 256];
__device__ __nv_bfloat16 g_wtop_h[256 * 256],  g_wtop_l[256 * 256];
__device__ __nv_bfloat16 g_wbot_h[256 * 256],  g_wbot_l[256 * 256];
__device__ __nv_bfloat16 g_ctx_h [256 * 256],  g_ctx_l [256 * 256];
__device__ __nv_bfloat16 g_att_h [256 * 128],  g_att_l [256 * 128];
__device__ __nv_bfloat16 g_out_h [1088 * 256], g_out_l [1088 * 256];

// ---------------- cp.async helpers ----------------
__device__ __forceinline__ void cp16(uint32_t dst, const void* src) {
    asm volatile("cp.async.cg.shared.global [%0], [%1], 16;"
                 :: "r"(dst), "l"(src));
}
#define CP_COMMIT() asm volatile("cp.async.commit_group;" ::: "memory")
#define CP_WAIT1()  asm volatile("cp.async.wait_group 1;" ::: "memory")
#define CP_WAIT0()  asm volatile("cp.async.wait_group 0;" ::: "memory")

__device__ __forceinline__ uint32_t smem_u32(const void* p) {
    uint32_t a;
    asm("{ .reg .u64 t; cvta.to.shared.u64 t, %1; cvt.u32.u64 %0, t; }"
        : "=r"(a) : "l"(p));
    return a;
}

__device__ __forceinline__ float warp_sum32(float v) {
    v += __shfl_xor_sync(0xffffffffu, v, 16);
    v += __shfl_xor_sync(0xffffffffu, v, 8);
    v += __shfl_xor_sync(0xffffffffu, v, 4);
    v += __shfl_xor_sync(0xffffffffu, v, 2);
    v += __shfl_xor_sync(0xffffffffu, v, 1);
    return v;
}

// ---------------- merged weight prep ---------------------------------------
__device__ __forceinline__ void prep_one(
    const float* __restrict__ W, int Ksrc, int N, int NT, int idx,
    __nv_bfloat16* __restrict__ bh, __nv_bfloat16* __restrict__ bl)
{
    int kpad = idx / NT;
    int n    = idx - kpad * NT;
    int ksrc; bool valid;
    if (kpad < 512) {
        int seg = kpad >> 8, w = kpad & 255;
        ksrc = seg * 250 + w;
        valid = (w < 250) && (ksrc < Ksrc);
    } else {
        ksrc = 500 + (kpad - 512);
        valid = ksrc < Ksrc;
    }
    float v = (valid && n < N) ? W[ksrc * N + n] : 0.f;
    __nv_bfloat16 h = __float2bfloat16(v);
    bh[idx] = h;
    bl[idx] = __float2bfloat16(v - __bfloat162float(h));
}

// segments: enc 65536 | top 65536 | bot 65536 | ctxW 65536 | att 32768 | out 278528
__global__ __launch_bounds__(256)
void prep_w_all(const float* __restrict__ enc_W, const float* __restrict__ core_W,
                const float* __restrict__ ctx_W, const float* __restrict__ att_W1,
                const float* __restrict__ out_W,
                __nv_bfloat16* ench, __nv_bfloat16* encl,
                __nv_bfloat16* toph, __nv_bfloat16* topl,
                __nv_bfloat16* both, __nv_bfloat16* botl,
                __nv_bfloat16* ctxh, __nv_bfloat16* ctxl,
                __nv_bfloat16* atth, __nv_bfloat16* attl,
                __nv_bfloat16* outh, __nv_bfloat16* outl)
{
    int idx = blockIdx.x * 256 + threadIdx.x;
    if (idx < 65536) {
        prep_one(enc_W, 250, 250, 256, idx, ench, encl);
    } else if (idx < 131072) {
        prep_one(core_W, 250, 250, 256, idx - 65536, toph, topl);
    } else if (idx < 196608) {
        prep_one(core_W + 250 * 250, 250, 250, 256, idx - 131072, both, botl);
    } else if (idx < 262144) {
        prep_one(ctx_W, 250, 250, 256, idx - 196608, ctxh, ctxl);
    } else if (idx < 294912) {
        prep_one(att_W1, 250, 100, 128, idx - 262144, atth, attl);
    } else if (idx < 573440) {
        prep_one(out_W, 1076, 250, 256, idx - 294912, outh, outl);
    }
}

// merged activation prep: state (BK x 250 -> 256) | x (BK x 576)
__global__ __launch_bounds__(256)
void prep_act(const float* __restrict__ state, const float* __restrict__ x,
              __nv_bfloat16* stah, __nv_bfloat16* stal,
              __nv_bfloat16* xh,   __nv_bfloat16* xl)
{
    int idx = blockIdx.x * 256 + threadIdx.x;
    const int NS = BK * 256;
    float v; __nv_bfloat16* ph; __nv_bfloat16* pl; int o;
    if (idx < NS) {
        int r = idx >> 8, c = idx & 255;
        v = (c < 250) ? state[(size_t)r * 250 + c] : 0.f;
        ph = stah; pl = stal; o = idx;
    } else {
        int j = idx - NS;
        if (j >= BK * 576) return;
        v = x[j];
        ph = xh; pl = xl; o = j;
    }
    __nv_bfloat16 h = __float2bfloat16(v);
    ph[o] = h;
    pl[o] = __float2bfloat16(v - __bfloat162float(h));
}

// ---------------- pair combine: core = LN(relu(F[b,i]+G[b,j]+b)) -----------
__global__ __launch_bounds__(256)
void combine_kernel(const float* __restrict__ F, const float* __restrict__ G,
                    const float* __restrict__ bias,
                    const float* __restrict__ gamma,
                    const float* __restrict__ beta,
                    __nv_bfloat16* __restrict__ coh,
                    __nv_bfloat16* __restrict__ col_)
{
    const int r    = blockIdx.x * 8 + (threadIdx.x >> 5);
    const int lane = threadIdx.x & 31;

    int bidx = r / (Kn * (Kn - 1));
    int rem  = r - bidx * (Kn * (Kn - 1));
    int i    = rem / (Kn - 1);
    int jj   = rem - i * (Kn - 1);
    int j    = jj + (jj >= i ? 1 : 0);

    const float* fr = F + (size_t)(bidx * Kn + i) * 256 + lane * 8;
    const float* gr = G + (size_t)(bidx * Kn + j) * 256 + lane * 8;

    float4 f0 = *(const float4*)(fr);
    float4 f1 = *(const float4*)(fr + 4);
    float4 g0 = *(const float4*)(gr);
    float4 g1 = *(const float4*)(gr + 4);

    float v[8];
    {
        const float* fa = &f0.x; const float* ga = &g0.x;
        #pragma unroll
        for (int t = 0; t < 4; ++t) {
            int c = lane * 8 + t;
            v[t] = (c < H1) ? fmaxf(fa[t] + ga[t] + bias[c], 0.f) : 0.f;
        }
        const float* fb = &f1.x; const float* gb = &g1.x;
        #pragma unroll
        for (int t = 0; t < 4; ++t) {
            int c = lane * 8 + 4 + t;
            v[4 + t] = (c < H1) ? fmaxf(fb[t] + gb[t] + bias[c], 0.f) : 0.f;
        }
    }

    float sum = 0.f, ssq = 0.f;
    #pragma unroll
    for (int t = 0; t < 8; ++t) { sum += v[t]; ssq += v[t] * v[t]; }
    sum = warp_sum32(sum);
    ssq = warp_sum32(ssq);
    float mu  = sum / (float)H1;
    float inv = rsqrtf(ssq / (float)H1 - mu * mu + EPS_LN);

    size_t o = (size_t)r * 256 + lane * 8;
    #pragma unroll
    for (int t = 0; t < 8; t += 2) {
        int c0 = lane * 8 + t, c1 = c0 + 1;
        float y0 = (c0 < H1) ? (v[t]     - mu) * inv * gamma[c0] + beta[c0] : 0.f;
        float y1 = (c1 < H1) ? (v[t + 1] - mu) * inv * gamma[c1] + beta[c1] : 0.f;
        __nv_bfloat16 h0 = __float2bfloat16(y0);
        __nv_bfloat16 h1 = __float2bfloat16(y1);
        __nv_bfloat16 l0 = __float2bfloat16(y0 - __bfloat162float(h0));
        __nv_bfloat16 l1 = __float2bfloat16(y1 - __bfloat162float(h1));
        *(__nv_bfloat162*)(coh  + o + t) = __nv_bfloat162(h0, h1);
        *(__nv_bfloat162*)(col_ + o + t) = __nv_bfloat162(l0, l1);
    }
}

// ---------------- fused wmma GEMM ------------------------------------------
// BM=128 rows per CTA, NT cols, K-chunk 64, 512 threads (16 warps), 1 CTA/SM.
// NT: padded N (256 / 128). N: logical cols. KDIM: padded K (mult of 64).
// ASRC: 0 direct (src width = KDIM), 2 tri-concat (s1 256 | eff 256 | x 576).
// ACT: 0 relu, 1 tanh, 2 none.
// OUT: 0 fp32 C, 1 bf16 hi/lo (width NT), 2 attention scalar.
// DUAL: grid doubled; second half of blocks uses B2h/B2l -> Cf2.
template <int NT, int N, int KDIM, int ASRC, int ACT, bool DO_LN, int OUT, bool DUAL>
__global__ __launch_bounds__(512, 1)
void tc_gemm(const __nv_bfloat16* __restrict__ Ah, const __nv_bfloat16* __restrict__ Al,
             const __nv_bfloat16* __restrict__ A2h, const __nv_bfloat16* __restrict__ A2l,
             const __nv_bfloat16* __restrict__ A3h, const __nv_bfloat16* __restrict__ A3l,
             const __nv_bfloat16* __restrict__ Bh0, const __nv_bfloat16* __restrict__ Bl0,
             const __nv_bfloat16* __restrict__ B2h, const __nv_bfloat16* __restrict__ B2l,
             const float* __restrict__ bias, const float* __restrict__ gamma,
             const float* __restrict__ beta, const float* __restrict__ W2,
             const float* __restrict__ b2,
             float* __restrict__ Cf0, float* __restrict__ Cf2,
             __nv_bfloat16* __restrict__ Ch, __nv_bfloat16* __restrict__ Cl, int ldc)
{
    constexpr int KCH  = 64;
    constexpr int KC   = KDIM / KCH;
    constexpr int LDA  = 72;                 // elems (144B rows: bank rotation)
    constexpr int LDB  = NT + 8;
    constexpr int CLD  = NT + 8;
    constexpr int A_BYTES = 128 * LDA * 2;   // 18432
    constexpr int B_BYTES = KCH * LDB * 2;
    constexpr int STG  = 2 * A_BYTES + 2 * B_BYTES;
    constexpr int WN   = NT / 64;            // warps along n (4 / 2)
    constexpr int WM   = 16 / WN;            // warps along m (4 / 8)
    constexpr int MROW = 128 / WM;           // rows per warp (32 / 16)
    constexpr int MF   = MROW / 16;          // m frags (2 / 1)
    constexpr int NF   = 4;                  // n frags (64 cols)

    extern __shared__ char smem[];
    const uint32_t sb = smem_u32(smem);

    const int tid = threadIdx.x;
    const int wid = tid >> 5;

    int blk = blockIdx.x;
    bool second = false;
    if (DUAL) {
        const int half = (int)gridDim.x >> 1;
        second = blk >= half;
        if (second) blk -= half;
    }
    const int rowBase = blk * 128;
    const __nv_bfloat16* Bh = (DUAL && second) ? B2h : Bh0;
    const __nv_bfloat16* Bl = (DUAL && second) ? B2l : Bl0;
    float* Cf = (DUAL && second) ? Cf2 : Cf0;

    // ---- async stage of one 64-k chunk (A h/l + B h/l, pure 16B copies) ----
    auto stage = [&](int c) {
        const int st = c & 1;
        const uint32_t ah = sb + st * STG;
        const uint32_t al = ah + A_BYTES;
        const uint32_t bh = al + A_BYTES;
        const uint32_t bl = bh + B_BYTES;
        // A: 128 rows x 8 k16-units = 1024 units
        #pragma unroll
        for (int i = 0; i < 2; ++i) {
            int u   = tid + i * 512;
            int row = u >> 3, k16 = u & 7;
            const __nv_bfloat16 *sh, *sl;
            int off;
            size_t r = (size_t)(rowBase + row);
            if (ASRC == 0) {
                sh = Ah + r * KDIM; sl = Al + r * KDIM;
                off = c * KCH + k16 * 8;
            } else {
                if (c < 4)      { sh = Ah  + r * 256; sl = Al  + r * 256; off = c * KCH + k16 * 8; }
                else if (c < 8) { sh = A2h + r * 256; sl = A2l + r * 256; off = (c - 4) * KCH + k16 * 8; }
                else            { sh = A3h + r * 576; sl = A3l + r * 576; off = (c - 8) * KCH + k16 * 8; }
            }
            uint32_t d = (uint32_t)(row * (LDA * 2) + k16 * 16);
            cp16(ah + d, sh + off);
            cp16(al + d, sl + off);
        }
        // B: KCH rows x NT/8 units
        #pragma unroll
        for (int i = 0; i < (KCH * NT / 8) / 512; ++i) {
            int u   = tid + i * 512;
            int kk  = u / (NT / 8), n16 = u % (NT / 8);
            size_t go = (size_t)(c * KCH + kk) * NT + n16 * 8;
            uint32_t d = (uint32_t)(kk * (LDB * 2) + n16 * 16);
            cp16(bh + d, Bh + go);
            cp16(bl + d, Bl + go);
        }
    };

    const int wm = wid / WN, wn = wid % WN;
    const int mrow0 = wm * MROW, ncol0 = wn * 64;

    wmma::fragment<wmma::accumulator, 16, 16, 16, float> acc[MF][NF];
    #pragma unroll
    for (int i = 0; i < MF; ++i)
        #pragma unroll
        for (int j = 0; j < NF; ++j)
            wmma::fill_fragment(acc[i][j], 0.f);

    stage(0); CP_COMMIT();

    for (int c = 0; c < KC; ++c) {
        if (c + 1 < KC) { stage(c + 1); CP_COMMIT(); CP_WAIT1(); }
        else            { CP_WAIT0(); }
        __syncthreads();

        const int st = c & 1;
        const __nv_bfloat16* Ash = (const __nv_bfloat16*)(smem + st * STG);
        const __nv_bfloat16* Asl = Ash + 128 * LDA;
        const __nv_bfloat16* Bsh = Asl + 128 * LDA;
        const __nv_bfloat16* Bsl = Bsh + KCH * LDB;

        #pragma unroll
        for (int s = 0; s < KCH / 16; ++s) {
            wmma::fragment<wmma::matrix_a, 16, 16, 16, __nv_bfloat16, wmma::row_major> ah[MF], al[MF];
            #pragma unroll
            for (int i = 0; i < MF; ++i) {
                wmma::load_matrix_sync(ah[i], Ash + (mrow0 + i * 16) * LDA + s * 16, LDA);
                wmma::load_matrix_sync(al[i], Asl + (mrow0 + i * 16) * LDA + s * 16, LDA);
            }
            #pragma unroll
            for (int j = 0; j < NF; ++j) {
                wmma::fragment<wmma::matrix_b, 16, 16, 16, __nv_bfloat16, wmma::row_major> bh, bl;
                wmma::load_matrix_sync(bh, Bsh + (s * 16) * LDB + ncol0 + j * 16, LDB);
                wmma::load_matrix_sync(bl, Bsl + (s * 16) * LDB + ncol0 + j * 16, LDB);
                #pragma unroll
                for (int i = 0; i < MF; ++i) {
                    wmma::mma_sync(acc[i][j], ah[i], bh, acc[i][j]);
                    wmma::mma_sync(acc[i][j], ah[i], bl, acc[i][j]);
                    wmma::mma_sync(acc[i][j], al[i], bh, acc[i][j]);
                }
            }
        }
        __syncthreads();
    }

    // ---- dump accumulators to SMEM fp32 ----
    float* Cs = (float*)smem;
    #pragma unroll
    for (int i = 0; i < MF; ++i)
        #pragma unroll
        for (int j = 0; j < NF; ++j)
            wmma::store_matrix_sync(Cs + (mrow0 + i * 16) * CLD + ncol0 + j * 16,
                                    acc[i][j], CLD, wmma::mem_row_major);
    __syncthreads();

    // 4 threads per row (128 rows), each owns HC contiguous cols
    constexpr int HC = NT / 4;
    float* muS  = (float*)(smem + 128 * CLD * 4);
    float* invS = muS + 128;

    const int row = tid >> 2, qq = tid & 3;
    const float* crow = Cs + row * CLD + qq * HC;

    if constexpr (OUT == 2) {
        float sum = 0.f, ssq = 0.f;
        #pragma unroll 4
        for (int j = 0; j < HC; ++j) {
            int cc = qq * HC + j;
            float v = 0.f;
            if (cc < N) { v = tanhf(crow[j] + bias[cc]); }
            sum += v; ssq += v * v;
        }
        float s = sum, q = ssq;
        s += __shfl_xor_sync(0xffffffffu, s, 1); s += __shfl_xor_sync(0xffffffffu, s, 2);
        q += __shfl_xor_sync(0xffffffffu, q, 1); q += __shfl_xor_sync(0xffffffffu, q, 2);
        float mu  = s / (float)N;
        float inv = rsqrtf(q / (float)N - mu * mu + EPS_LN);
        float d = 0.f;
        #pragma unroll 4
        for (int j = 0; j < HC; ++j) {
            int cc = qq * HC + j;
            if (cc < N) {
                float v = tanhf(crow[j] + bias[cc]);
                v = (v - mu) * inv * gamma[cc] + beta[cc];
                d += v * W2[cc];
            }
        }
        d += __shfl_xor_sync(0xffffffffu, d, 1);
        d += __shfl_xor_sync(0xffffffffu, d, 2);
        if (qq == 0) {
            float z = d + b2[0];
            Cf[rowBase + row] = 1.f / (1.f + expf(-z));
        }
    } else {
        if constexpr (DO_LN) {
            float sum = 0.f, ssq = 0.f;
            #pragma unroll 4
            for (int j = 0; j < HC; ++j) {
                int cc = qq * HC + j;
                float v = 0.f;
                if (cc < N) {
                    v = crow[j] + bias[cc];
                    if (ACT == 0)      v = fmaxf(v, 0.f);
                    else if (ACT == 1) v = tanhf(v);
                }
                sum += v; ssq += v * v;
            }
            float s = sum, q = ssq;
            s += __shfl_xor_sync(0xffffffffu, s, 1); s += __shfl_xor_sync(0xffffffffu, s, 2);
            q += __shfl_xor_sync(0xffffffffu, q, 1); q += __shfl_xor_sync(0xffffffffu, q, 2);
            if (qq == 0) {
                float mu = s / (float)N;
                muS[row]  = mu;
                invS[row] = rsqrtf(q / (float)N - mu * mu + EPS_LN);
            }
            __syncthreads();
        }
        for (int e = tid * 2; e < 128 * NT; e += 1024) {
            int rr2 = e / NT;
            int col = e - rr2 * NT;
            float mu = 0.f, iv = 0.f;
            if (DO_LN) { mu = muS[rr2]; iv = invS[rr2]; }
            float v[2];
            #pragma unroll
            for (int t = 0; t < 2; ++t) {
                int cc = col + t;
                float xv = 0.f;
                if (cc < N) {
                    xv = Cs[rr2 * CLD + cc] + bias[cc];
                    if (ACT == 0)      xv = fmaxf(xv, 0.f);
                    else if (ACT == 1) xv = tanhf(xv);
                    if (DO_LN)
                        xv = (xv - mu) * iv * gamma[cc] + beta[cc];
                }
                v[t] = xv;
            }
            if (OUT == 1) {
                __nv_bfloat16 h0 = __float2bfloat16(v[0]);
                __nv_bfloat16 h1 = __float2bfloat16(v[1]);
                __nv_bfloat16 l0 = __float2bfloat16(v[0] - __bfloat162float(h0));
                __nv_bfloat16 l1 = __float2bfloat16(v[1] - __bfloat162float(h1));
                size_t o = (size_t)(rowBase + rr2) * NT + col;
                *(__nv_bfloat162*)(Ch + o) = __nv_bfloat162(h0, h1);
                *(__nv_bfloat162*)(Cl + o) = __nv_bfloat162(l0, l1);
            } else {
                size_t o = (size_t)(rowBase + rr2) * ldc + col;
                if (col < N)     Cf[o]     = v[0];
                if (col + 1 < N) Cf[o + 1] = v[1];
            }
        }
    }
}

// eff[bk, c] = sum_{j<7} ctx[bk*7+j, c] * att[bk*7+j]; emit bf16 hi/lo pad-256
__global__ __launch_bounds__(256)
void effect_kernel(const float* __restrict__ ctx,
                   const float* __restrict__ att,
                   __nv_bfloat16* __restrict__ effh,
                   __nv_bfloat16* __restrict__ effl)
{
    const int bk = blockIdx.x;
    __shared__ float a[Kn - 1];
    if (threadIdx.x < Kn - 1) a[threadIdx.x] = att[bk * (Kn - 1) + threadIdx.x];
    __syncthreads();
    int c = threadIdx.x;
    float s = 0.f;
    if (c < H1) {
        const float* base = ctx + (size_t)bk * (Kn - 1) * H1;
        #pragma unroll
        for (int j = 0; j < Kn - 1; ++j)
            s = fmaf(base[j * H1 + c], a[j], s);
    }
    __nv_bfloat16 h = __float2bfloat16(s);
    effh[(size_t)bk * 256 + c] = h;
    effl[(size_t)bk * 256 + c] = __float2bfloat16(s - __bfloat162float(h));
}

extern "C" void kernel_launch(void* const* d_in, const int* in_sizes, int n_in,
                              void* d_out, int out_size)
{
    const float* x      = (const float*)d_in[0];
    const float* state  = (const float*)d_in[1];
    const float* enc_W  = (const float*)d_in[2];
    const float* enc_b  = (const float*)d_in[3];
    const float* enc_g  = (const float*)d_in[4];
    const float* enc_bt = (const float*)d_in[5];
    const float* core_W = (const float*)d_in[6];
    const float* core_b = (const float*)d_in[7];
    const float* core_g = (const float*)d_in[8];
    const float* core_bt= (const float*)d_in[9];
    const float* ctx_W  = (const float*)d_in[10];
    const float* ctx_b  = (const float*)d_in[11];
    const float* ctx_g  = (const float*)d_in[12];
    const float* ctx_bt = (const float*)d_in[13];
    const float* att_W1 = (const float*)d_in[14];
    const float* att_b1 = (const float*)d_in[15];
    const float* att_g  = (const float*)d_in[16];
    const float* att_bt = (const float*)d_in[17];
    const float* att_W2 = (const float*)d_in[18];
    const float* att_b2 = (const float*)d_in[19];
    const float* out_W  = (const float*)d_in[20];
    const float* out_b  = (const float*)d_in[21];
    float* out = (float*)d_out;

    float *p_F, *p_G, *p_ctx, *p_att, *p_zero;
    cudaGetSymbolAddress((void**)&p_F,    g_F);
    cudaGetSymbolAddress((void**)&p_G,    g_G);
    cudaGetSymbolAddress((void**)&p_ctx,  g_ctx);
    cudaGetSymbolAddress((void**)&p_att,  g_att);
    cudaGetSymbolAddress((void**)&p_zero, g_zeros);

    __nv_bfloat16 *stah, *stal, *xh, *xl, *s1h, *s1l, *coh, *col_, *efh, *efl;
    cudaGetSymbolAddress((void**)&stah, g_sta_h); cudaGetSymbolAddress((void**)&stal, g_sta_l);
    cudaGetSymbolAddress((void**)&xh,   g_x_h);   cudaGetSymbolAddress((void**)&xl,   g_x_l);
    cudaGetSymbolAddress((void**)&s1h,  g_s1_h);  cudaGetSymbolAddress((void**)&s1l,  g_s1_l);
    cudaGetSymbolAddress((void**)&coh,  g_co_h);  cudaGetSymbolAddress((void**)&col_, g_co_l);
    cudaGetSymbolAddress((void**)&efh,  g_ef_h);  cudaGetSymbolAddress((void**)&efl,  g_ef_l);

    __nv_bfloat16 *ench, *encl, *toph, *topl, *both, *botl,
                  *ctxh, *ctxl, *atth, *attl, *outh, *outl;
    cudaGetSymbolAddress((void**)&ench, g_enc_h);  cudaGetSymbolAddress((void**)&encl, g_enc_l);
    cudaGetSymbolAddress((void**)&toph, g_wtop_h); cudaGetSymbolAddress((void**)&topl, g_wtop_l);
    cudaGetSymbolAddress((void**)&both, g_wbot_h); cudaGetSymbolAddress((void**)&botl, g_wbot_l);
    cudaGetSymbolAddress((void**)&ctxh, g_ctx_h);  cudaGetSymbolAddress((void**)&ctxl, g_ctx_l);
    cudaGetSymbolAddress((void**)&atth, g_att_h);  cudaGetSymbolAddress((void**)&attl, g_att_l);
    cudaGetSymbolAddress((void**)&outh, g_out_h);  cudaGetSymbolAddress((void**)&outl, g_out_l);

    // SMEM: 2 stages x (2*A(18432) + 2*B); NT=256: B=33792 -> 208896;
    //       NT=128: B=17408 -> 143360. Epilogue Cs fits inside stage region.
    constexpr int SM256 = 2 * (2 * 18432 + 2 * 33792) + 2048;   // 210944
    constexpr int SM128 = 2 * (2 * 18432 + 2 * 17408) + 2048;   // 145408
    cudaFuncSetAttribute(tc_gemm<256, 250, 256,  0, 0, true,  1, false>,
                         cudaFuncAttributeMaxDynamicSharedMemorySize, SM256);
    cudaFuncSetAttribute(tc_gemm<256, 250, 256,  0, 2, false, 0, true>,
                         cudaFuncAttributeMaxDynamicSharedMemorySize, SM256);
    cudaFuncSetAttribute(tc_gemm<256, 250, 256,  0, 0, true,  0, false>,
                         cudaFuncAttributeMaxDynamicSharedMemorySize, SM256);
    cudaFuncSetAttribute(tc_gemm<128, 100, 256,  0, 1, true,  2, false>,
                         cudaFuncAttributeMaxDynamicSharedMemorySize, SM128);
    cudaFuncSetAttribute(tc_gemm<256, 250, 1088, 2, 2, false, 0, false>,
                         cudaFuncAttributeMaxDynamicSharedMemorySize, SM256);

    // #1: all weight prep
    prep_w_all<<<(573440 + 255) / 256, 256>>>(
        enc_W, core_W, ctx_W, att_W1, out_W,
        ench, encl, toph, topl, both, botl, ctxh, ctxl, atth, attl, outh, outl);

    // #2: activation prep (state + x)
    prep_act<<<(BK * 256 + BK * 576 + 255) / 256, 256>>>(state, x, stah, stal, xh, xl);

    // #3: s1 = LN(relu(state @ enc_W + b)) -> bf16 hi/lo
    tc_gemm<256, 250, 256, 0, 0, true, 1, false><<<BK / 128, 512, SM256>>>(
        stah, stal, nullptr, nullptr, nullptr, nullptr, ench, encl, nullptr, nullptr,
        enc_b, enc_g, enc_bt, nullptr, nullptr, nullptr, nullptr, s1h, s1l, 0);

    // #4: F = s1 @ W_top AND G = s1 @ W_bot (dual-B, one launch)
    tc_gemm<256, 250, 256, 0, 2, false, 0, true><<<2 * (BK / 128), 512, SM256>>>(
        s1h, s1l, nullptr, nullptr, nullptr, nullptr, toph, topl, both, botl,
        p_zero, nullptr, nullptr, nullptr, nullptr, p_F, p_G, nullptr, nullptr, 256);

    // #5: core = LN(relu(F[b,i] + G[b,j] + b)) -> bf16 hi/lo
    combine_kernel<<<RR / 8, 256>>>(p_F, p_G, core_b, core_g, core_bt, coh, col_);

    // #6 (ncu capture window): ctx = LN(relu(core @ ctx_W + b)) -> fp32
    tc_gemm<256, 250, 256, 0, 0, true, 0, false><<<RR / 128, 512, SM256>>>(
        coh, col_, nullptr, nullptr, nullptr, nullptr, ctxh, ctxl, nullptr, nullptr,
        ctx_b, ctx_g, ctx_bt, nullptr, nullptr, p_ctx, nullptr, nullptr, nullptr, H1);

    // #7: att = sigmoid(LN(tanh(core @ att_W1 + b1)) @ att_W2 + b2)
    tc_gemm<128, 100, 256, 0, 1, true, 2, false><<<RR / 128, 512, SM128>>>(
        coh, col_, nullptr, nullptr, nullptr, nullptr, atth, attl, nullptr, nullptr,
        att_b1, att_g, att_bt, att_W2, att_b2, p_att, nullptr, nullptr, nullptr, 0);

    // #8: eff = 7-way attention-weighted reduction of ctx -> bf16 hi/lo
    effect_kernel<<<BK, 256>>>(p_ctx, p_att, efh, efl);

    // #9: out = concat(s1, eff, x) @ out_W + out_b -> fp32 d_out
    tc_gemm<256, 250, 1088, 2, 2, false, 0, false><<<BK / 128, 512, SM256>>>(
        s1h, s1l, efh, efl, xh, xl, outh, outl, nullptr, nullptr,
        out_b, nullptr, nullptr, nullptr, nullptr, out, nullptr, nullptr, nullptr, H1);
}

// round 12
// speedup vs baseline: 1.6079x; 1.6079x over previous
#include <cuda_runtime.h>
#include <cuda_bf16.h>
#include <mma.h>
#include <math.h>
#include <stdint.h>

using namespace nvcuda;

// ---------------------------------------------------------------------------
// R-NEM cell on tensor cores (wmma bf16 HMMA; tcgen05 unavailable on the
// harness's compute_103 PTX target). fp32 emulated as bf16 hi/lo 3-term.
// R11: revert to the measured-best R8 geometry (BM=128, 256 threads, KCH=64,
//      1 CTA/SM) — R9/R10 occupancy experiments both regressed; tensor% is
//      insensitive to occ/regs => near the legacy-HMMA ceiling. One edit:
//      term-major mma ordering (same-acc reuse distance 1 -> MF).
// ---------------------------------------------------------------------------

#define EPS_LN 1e-5f

static constexpr int Bn  = 2048;
static constexpr int Kn  = 8;
static constexpr int BK  = Bn * Kn;          // 16384 entity rows
static constexpr int RR  = BK * (Kn - 1);    // 114688 pair rows
static constexpr int H1  = 250;
static constexpr int Mx  = 576;

// fp32 scratch
__device__ float g_F  [BK * 256];
__device__ float g_G  [BK * 256];
__device__ float g_ctx[RR * H1];
__device__ float g_att[RR];
__device__ float g_zeros[256];               // zero bias for F/G GEMMs

// bf16 hi/lo activations (k-padded, zero-filled pad)
__device__ __nv_bfloat16 g_sta_h[BK * 256], g_sta_l[BK * 256];
__device__ __nv_bfloat16 g_x_h  [BK * 576], g_x_l  [BK * 576];
__device__ __nv_bfloat16 g_s1_h [BK * 256], g_s1_l [BK * 256];
__device__ __nv_bfloat16 g_co_h [RR * 256], g_co_l [RR * 256];
__device__ __nv_bfloat16 g_ef_h [BK * 256], g_ef_l [BK * 256];

// Pre-split weights, [Kpad][NT] row-major; 250-wide K segments padded to 256.
__device__ __nv_bfloat16 g_enc_h [256 * 256],  g_enc_l [256 * 256];
__device__ __nv_bfloat16 g_wtop_h[256 * 256],  g_wtop_l[256 * 256];
__device__ __nv_bfloat16 g_wbot_h[256 * 256],  g_wbot_l[256 * 256];
__device__ __nv_bfloat16 g_ctx_h [256 * 256],  g_ctx_l [256 * 256];
__device__ __nv_bfloat16 g_att_h [256 * 128],  g_att_l [256 * 128];
__device__ __nv_bfloat16 g_out_h [1088 * 256], g_out_l [1088 * 256];

// ---------------- cp.async helpers ----------------
__device__ __forceinline__ void cp16(uint32_t dst, const void* src) {
    asm volatile("cp.async.cg.shared.global [%0], [%1], 16;"
                 :: "r"(dst), "l"(src));
}
#define CP_COMMIT() asm volatile("cp.async.commit_group;" ::: "memory")
#define CP_WAIT1()  asm volatile("cp.async.wait_group 1;" ::: "memory")
#define CP_WAIT0()  asm volatile("cp.async.wait_group 0;" ::: "memory")

__device__ __forceinline__ uint32_t smem_u32(const void* p) {
    uint32_t a;
    asm("{ .reg .u64 t; cvta.to.shared.u64 t, %1; cvt.u32.u64 %0, t; }"
        : "=r"(a) : "l"(p));
    return a;
}

__device__ __forceinline__ float warp_sum32(float v) {
    v += __shfl_xor_sync(0xffffffffu, v, 16);
    v += __shfl_xor_sync(0xffffffffu, v, 8);
    v += __shfl_xor_sync(0xffffffffu, v, 4);
    v += __shfl_xor_sync(0xffffffffu, v, 2);
    v += __shfl_xor_sync(0xffffffffu, v, 1);
    return v;
}

// ---------------- merged weight prep ---------------------------------------
__device__ __forceinline__ void prep_one(
    const float* __restrict__ W, int Ksrc, int N, int NT, int idx,
    __nv_bfloat16* __restrict__ bh, __nv_bfloat16* __restrict__ bl)
{
    int kpad = idx / NT;
    int n    = idx - kpad * NT;
    int ksrc; bool valid;
    if (kpad < 512) {
        int seg = kpad >> 8, w = kpad & 255;
        ksrc = seg * 250 + w;
        valid = (w < 250) && (ksrc < Ksrc);
    } else {
        ksrc = 500 + (kpad - 512);
        valid = ksrc < Ksrc;
    }
    float v = (valid && n < N) ? W[ksrc * N + n] : 0.f;
    __nv_bfloat16 h = __float2bfloat16(v);
    bh[idx] = h;
    bl[idx] = __float2bfloat16(v - __bfloat162float(h));
}

// segments: enc 65536 | top 65536 | bot 65536 | ctxW 65536 | att 32768 | out 278528
__global__ __launch_bounds__(256)
void prep_w_all(const float* __restrict__ enc_W, const float* __restrict__ core_W,
                const float* __restrict__ ctx_W, const float* __restrict__ att_W1,
                const float* __restrict__ out_W,
                __nv_bfloat16* ench, __nv_bfloat16* encl,
                __nv_bfloat16* toph, __nv_bfloat16* topl,
                __nv_bfloat16* both, __nv_bfloat16* botl,
                __nv_bfloat16* ctxh, __nv_bfloat16* ctxl,
                __nv_bfloat16* atth, __nv_bfloat16* attl,
                __nv_bfloat16* outh, __nv_bfloat16* outl)
{
    int idx = blockIdx.x * 256 + threadIdx.x;
    if (idx < 65536) {
        prep_one(enc_W, 250, 250, 256, idx, ench, encl);
    } else if (idx < 131072) {
        prep_one(core_W, 250, 250, 256, idx - 65536, toph, topl);
    } else if (idx < 196608) {
        prep_one(core_W + 250 * 250, 250, 250, 256, idx - 131072, both, botl);
    } else if (idx < 262144) {
        prep_one(ctx_W, 250, 250, 256, idx - 196608, ctxh, ctxl);
    } else if (idx < 294912) {
        prep_one(att_W1, 250, 100, 128, idx - 262144, atth, attl);
    } else if (idx < 573440) {
        prep_one(out_W, 1076, 250, 256, idx - 294912, outh, outl);
    }
}

// merged activation prep: state (BK x 250 -> 256) | x (BK x 576)
__global__ __launch_bounds__(256)
void prep_act(const float* __restrict__ state, const float* __restrict__ x,
              __nv_bfloat16* stah, __nv_bfloat16* stal,
              __nv_bfloat16* xh,   __nv_bfloat16* xl)
{
    int idx = blockIdx.x * 256 + threadIdx.x;
    const int NS = BK * 256;
    float v; __nv_bfloat16* ph; __nv_bfloat16* pl; int o;
    if (idx < NS) {
        int r = idx >> 8, c = idx & 255;
        v = (c < 250) ? state[(size_t)r * 250 + c] : 0.f;
        ph = stah; pl = stal; o = idx;
    } else {
        int j = idx - NS;
        if (j >= BK * 576) return;
        v = x[j];
        ph = xh; pl = xl; o = j;
    }
    __nv_bfloat16 h = __float2bfloat16(v);
    ph[o] = h;
    pl[o] = __float2bfloat16(v - __bfloat162float(h));
}

// ---------------- pair combine: core = LN(relu(F[b,i]+G[b,j]+b)) -----------
__global__ __launch_bounds__(256)
void combine_kernel(const float* __restrict__ F, const float* __restrict__ G,
                    const float* __restrict__ bias,
                    const float* __restrict__ gamma,
                    const float* __restrict__ beta,
                    __nv_bfloat16* __restrict__ coh,
                    __nv_bfloat16* __restrict__ col_)
{
    const int r    = blockIdx.x * 8 + (threadIdx.x >> 5);
    const int lane = threadIdx.x & 31;

    int bidx = r / (Kn * (Kn - 1));
    int rem  = r - bidx * (Kn * (Kn - 1));
    int i    = rem / (Kn - 1);
    int jj   = rem - i * (Kn - 1);
    int j    = jj + (jj >= i ? 1 : 0);

    const float* fr = F + (size_t)(bidx * Kn + i) * 256 + lane * 8;
    const float* gr = G + (size_t)(bidx * Kn + j) * 256 + lane * 8;

    float4 f0 = *(const float4*)(fr);
    float4 f1 = *(const float4*)(fr + 4);
    float4 g0 = *(const float4*)(gr);
    float4 g1 = *(const float4*)(gr + 4);

    float v[8];
    {
        const float* fa = &f0.x; const float* ga = &g0.x;
        #pragma unroll
        for (int t = 0; t < 4; ++t) {
            int c = lane * 8 + t;
            v[t] = (c < H1) ? fmaxf(fa[t] + ga[t] + bias[c], 0.f) : 0.f;
        }
        const float* fb = &f1.x; const float* gb = &g1.x;
        #pragma unroll
        for (int t = 0; t < 4; ++t) {
            int c = lane * 8 + 4 + t;
            v[4 + t] = (c < H1) ? fmaxf(fb[t] + gb[t] + bias[c], 0.f) : 0.f;
        }
    }

    float sum = 0.f, ssq = 0.f;
    #pragma unroll
    for (int t = 0; t < 8; ++t) { sum += v[t]; ssq += v[t] * v[t]; }
    sum = warp_sum32(sum);
    ssq = warp_sum32(ssq);
    float mu  = sum / (float)H1;
    float inv = rsqrtf(ssq / (float)H1 - mu * mu + EPS_LN);

    size_t o = (size_t)r * 256 + lane * 8;
    #pragma unroll
    for (int t = 0; t < 8; t += 2) {
        int c0 = lane * 8 + t, c1 = c0 + 1;
        float y0 = (c0 < H1) ? (v[t]     - mu) * inv * gamma[c0] + beta[c0] : 0.f;
        float y1 = (c1 < H1) ? (v[t + 1] - mu) * inv * gamma[c1] + beta[c1] : 0.f;
        __nv_bfloat16 h0 = __float2bfloat16(y0);
        __nv_bfloat16 h1 = __float2bfloat16(y1);
        __nv_bfloat16 l0 = __float2bfloat16(y0 - __bfloat162float(h0));
        __nv_bfloat16 l1 = __float2bfloat16(y1 - __bfloat162float(h1));
        *(__nv_bfloat162*)(coh  + o + t) = __nv_bfloat162(h0, h1);
        *(__nv_bfloat162*)(col_ + o + t) = __nv_bfloat162(l0, l1);
    }
}

// ---------------- fused wmma GEMM ------------------------------------------
// BM=128, NT cols, K-chunk 64, 256 threads (8 warps), 1 CTA/SM (R8 geometry).
// NT: padded N (256 / 128). N: logical cols. KDIM: padded K (mult of 64).
// ASRC: 0 direct (src width = KDIM), 2 tri-concat (s1 256 | eff 256 | x 576).
// ACT: 0 relu, 1 tanh, 2 none.
// OUT: 0 fp32 C, 1 bf16 hi/lo (width NT), 2 attention scalar.
// DUAL: grid doubled; second half of blocks uses B2h/B2l -> Cf2.
template <int NT, int N, int KDIM, int ASRC, int ACT, bool DO_LN, int OUT, bool DUAL>
__global__ __launch_bounds__(256, 1)
void tc_gemm(const __nv_bfloat16* __restrict__ Ah, const __nv_bfloat16* __restrict__ Al,
             const __nv_bfloat16* __restrict__ A2h, const __nv_bfloat16* __restrict__ A2l,
             const __nv_bfloat16* __restrict__ A3h, const __nv_bfloat16* __restrict__ A3l,
             const __nv_bfloat16* __restrict__ Bh0, const __nv_bfloat16* __restrict__ Bl0,
             const __nv_bfloat16* __restrict__ B2h, const __nv_bfloat16* __restrict__ B2l,
             const float* __restrict__ bias, const float* __restrict__ gamma,
             const float* __restrict__ beta, const float* __restrict__ W2,
             const float* __restrict__ b2,
             float* __restrict__ Cf0, float* __restrict__ Cf2,
             __nv_bfloat16* __restrict__ Ch, __nv_bfloat16* __restrict__ Cl, int ldc)
{
    constexpr int KCH  = 64;
    constexpr int KC   = KDIM / KCH;
    constexpr int LDA  = 72;                 // elems (144B rows: bank rotation)
    constexpr int LDB  = NT + 8;
    constexpr int CLD  = NT + 8;
    constexpr int A_BYTES = 128 * LDA * 2;   // 18432
    constexpr int B_BYTES = KCH * LDB * 2;
    constexpr int STG  = 2 * A_BYTES + 2 * B_BYTES;
    constexpr int WN   = NT / 64;            // warps along n
    constexpr int WM   = 8 / WN;             // warps along m
    constexpr int MROW = 128 / WM;           // rows per warp
    constexpr int MF   = MROW / 16;          // m frags
    constexpr int NF   = 4;                  // n frags (64 cols)

    extern __shared__ char smem[];
    const uint32_t sb = smem_u32(smem);

    const int tid = threadIdx.x;
    const int wid = tid >> 5;

    int blk = blockIdx.x;
    bool second = false;
    if (DUAL) {
        const int half = (int)gridDim.x >> 1;
        second = blk >= half;
        if (second) blk -= half;
    }
    const int rowBase = blk * 128;
    const __nv_bfloat16* Bh = (DUAL && second) ? B2h : Bh0;
    const __nv_bfloat16* Bl = (DUAL && second) ? B2l : Bl0;
    float* Cf = (DUAL && second) ? Cf2 : Cf0;

    // ---- async stage of one 64-k chunk (A h/l + B h/l, pure 16B copies) ----
    auto stage = [&](int c) {
        const int st = c & 1;
        const uint32_t ah = sb + st * STG;
        const uint32_t al = ah + A_BYTES;
        const uint32_t bh = al + A_BYTES;
        const uint32_t bl = bh + B_BYTES;
        #pragma unroll
        for (int i = 0; i < 4; ++i) {              // 1024 A-units per matrix
            int u   = tid + i * 256;
            int row = u >> 3, k16 = u & 7;
            const __nv_bfloat16 *sh, *sl;
            int off;
            size_t r = (size_t)(rowBase + row);
            if (ASRC == 0) {
                sh = Ah + r * KDIM; sl = Al + r * KDIM;
                off = c * KCH + k16 * 8;
            } else {
                if (c < 4)      { sh = Ah  + r * 256; sl = Al  + r * 256; off = c * KCH + k16 * 8; }
                else if (c < 8) { sh = A2h + r * 256; sl = A2l + r * 256; off = (c - 4) * KCH + k16 * 8; }
                else            { sh = A3h + r * 576; sl = A3l + r * 576; off = (c - 8) * KCH + k16 * 8; }
            }
            uint32_t d = (uint32_t)(row * (LDA * 2) + k16 * 16);
            cp16(ah + d, sh + off);
            cp16(al + d, sl + off);
        }
        #pragma unroll
        for (int i = 0; i < (KCH * NT / 8) / 256; ++i) {
            int u   = tid + i * 256;
            int kk  = u / (NT / 8), n16 = u % (NT / 8);
            size_t go = (size_t)(c * KCH + kk) * NT + n16 * 8;
            uint32_t d = (uint32_t)(kk * (LDB * 2) + n16 * 16);
            cp16(bh + d, Bh + go);
            cp16(bl + d, Bl + go);
        }
    };

    const int wm = wid / WN, wn = wid % WN;
    const int mrow0 = wm * MROW, ncol0 = wn * 64;

    wmma::fragment<wmma::accumulator, 16, 16, 16, float> acc[MF][NF];
    #pragma unroll
    for (int i = 0; i < MF; ++i)
        #pragma unroll
        for (int j = 0; j < NF; ++j)
            wmma::fill_fragment(acc[i][j], 0.f);

    stage(0); CP_COMMIT();

    for (int c = 0; c < KC; ++c) {
        if (c + 1 < KC) { stage(c + 1); CP_COMMIT(); CP_WAIT1(); }
        else            { CP_WAIT0(); }
        __syncthreads();

        const int st = c & 1;
        const __nv_bfloat16* Ash = (const __nv_bfloat16*)(smem + st * STG);
        const __nv_bfloat16* Asl = Ash + 128 * LDA;
        const __nv_bfloat16* Bsh = Asl + 128 * LDA;
        const __nv_bfloat16* Bsl = Bsh + KCH * LDB;

        #pragma unroll
        for (int s = 0; s < KCH / 16; ++s) {
            wmma::fragment<wmma::matrix_a, 16, 16, 16, __nv_bfloat16, wmma::row_major> ah[MF], al[MF];
            #pragma unroll
            for (int i = 0; i < MF; ++i) {
                wmma::load_matrix_sync(ah[i], Ash + (mrow0 + i * 16) * LDA + s * 16, LDA);
                wmma::load_matrix_sync(al[i], Asl + (mrow0 + i * 16) * LDA + s * 16, LDA);
            }
            #pragma unroll
            for (int j = 0; j < NF; ++j) {
                wmma::fragment<wmma::matrix_b, 16, 16, 16, __nv_bfloat16, wmma::row_major> bh, bl;
                wmma::load_matrix_sync(bh, Bsh + (s * 16) * LDB + ncol0 + j * 16, LDB);
                wmma::load_matrix_sync(bl, Bsl + (s * 16) * LDB + ncol0 + j * 16, LDB);
                // term-major: same-acc reuse distance = MF (was 1)
                #pragma unroll
                for (int i = 0; i < MF; ++i)
                    wmma::mma_sync(acc[i][j], ah[i], bh, acc[i][j]);
                #pragma unroll
                for (int i = 0; i < MF; ++i)
                    wmma::mma_sync(acc[i][j], ah[i], bl, acc[i][j]);
                #pragma unroll
                for (int i = 0; i < MF; ++i)
                    wmma::mma_sync(acc[i][j], al[i], bh, acc[i][j]);
            }
        }
        __syncthreads();
    }

    // ---- dump accumulators to SMEM fp32 ----
    float* Cs = (float*)smem;
    #pragma unroll
    for (int i = 0; i < MF; ++i)
        #pragma unroll
        for (int j = 0; j < NF; ++j)
            wmma::store_matrix_sync(Cs + (mrow0 + i * 16) * CLD + ncol0 + j * 16,
                                    acc[i][j], CLD, wmma::mem_row_major);
    __syncthreads();

    constexpr int HC = NT / 2;
    float* muS  = (float*)(smem + 128 * CLD * 4);
    float* invS = muS + 128;

    if constexpr (OUT == 2) {
        const int row = tid >> 1, hf = tid & 1;
        const float* crow = Cs + row * CLD + hf * HC;
        float sum = 0.f, ssq = 0.f;
        #pragma unroll 4
        for (int j = 0; j < HC; ++j) {
            int cc = hf * HC + j;
            float v = 0.f;
            if (cc < N) { v = tanhf(crow[j] + bias[cc]); }
            sum += v; ssq += v * v;
        }
        float s = sum + __shfl_xor_sync(0xffffffffu, sum, 1);
        float q = ssq + __shfl_xor_sync(0xffffffffu, ssq, 1);
        float mu = s / (float)N;
        float inv = rsqrtf(q / (float)N - mu * mu + EPS_LN);
        float d = 0.f;
        #pragma unroll 4
        for (int j = 0; j < HC; ++j) {
            int cc = hf * HC + j;
            if (cc < N) {
                float v = tanhf(crow[j] + bias[cc]);
                v = (v - mu) * inv * gamma[cc] + beta[cc];
                d += v * W2[cc];
            }
        }
        d += __shfl_xor_sync(0xffffffffu, d, 1);
        if (hf == 0) {
            float z = d + b2[0];
            Cf[rowBase + row] = 1.f / (1.f + expf(-z));
        }
    } else {
        if constexpr (DO_LN) {
            const int row = tid >> 1, hf = tid & 1;
            const float* crow = Cs + row * CLD + hf * HC;
            float sum = 0.f, ssq = 0.f;
            #pragma unroll 4
            for (int j = 0; j < HC; ++j) {
                int cc = hf * HC + j;
                float v = 0.f;
                if (cc < N) {
                    v = crow[j] + bias[cc];
                    if (ACT == 0)      v = fmaxf(v, 0.f);
                    else if (ACT == 1) v = tanhf(v);
                }
                sum += v; ssq += v * v;
            }
            float s = sum + __shfl_xor_sync(0xffffffffu, sum, 1);
            float q = ssq + __shfl_xor_sync(0xffffffffu, ssq, 1);
            if (hf == 0) {
                float mu = s / (float)N;
                muS[row]  = mu;
                invS[row] = rsqrtf(q / (float)N - mu * mu + EPS_LN);
            }
            __syncthreads();
        }
        for (int e = tid * 2; e < 128 * NT; e += 512) {
            int row = e / NT;
            int col = e - row * NT;
            float mu = 0.f, iv = 0.f;
            if (DO_LN) { mu = muS[row]; iv = invS[row]; }
            float v[2];
            #pragma unroll
            for (int t = 0; t < 2; ++t) {
                int cc = col + t;
                float xv = 0.f;
                if (cc < N) {
                    xv = Cs[row * CLD + cc] + bias[cc];
                    if (ACT == 0)      xv = fmaxf(xv, 0.f);
                    else if (ACT == 1) xv = tanhf(xv);
                    if (DO_LN)
                        xv = (xv - mu) * iv * gamma[cc] + beta[cc];
                }
                v[t] = xv;
            }
            if (OUT == 1) {
                __nv_bfloat16 h0 = __float2bfloat16(v[0]);
                __nv_bfloat16 h1 = __float2bfloat16(v[1]);
                __nv_bfloat16 l0 = __float2bfloat16(v[0] - __bfloat162float(h0));
                __nv_bfloat16 l1 = __float2bfloat16(v[1] - __bfloat162float(h1));
                size_t o = (size_t)(rowBase + row) * NT + col;
                *(__nv_bfloat162*)(Ch + o) = __nv_bfloat162(h0, h1);
                *(__nv_bfloat162*)(Cl + o) = __nv_bfloat162(l0, l1);
            } else {
                size_t o = (size_t)(rowBase + row) * ldc + col;
                if (col < N)     Cf[o]     = v[0];
                if (col + 1 < N) Cf[o + 1] = v[1];
            }
        }
    }
}

// eff[bk, c] = sum_{j<7} ctx[bk*7+j, c] * att[bk*7+j]; emit bf16 hi/lo pad-256
__global__ __launch_bounds__(256)
void effect_kernel(const float* __restrict__ ctx,
                   const float* __restrict__ att,
                   __nv_bfloat16* __restrict__ effh,
                   __nv_bfloat16* __restrict__ effl)
{
    const int bk = blockIdx.x;
    __shared__ float a[Kn - 1];
    if (threadIdx.x < Kn - 1) a[threadIdx.x] = att[bk * (Kn - 1) + threadIdx.x];
    __syncthreads();
    int c = threadIdx.x;
    float s = 0.f;
    if (c < H1) {
        const float* base = ctx + (size_t)bk * (Kn - 1) * H1;
        #pragma unroll
        for (int j = 0; j < Kn - 1; ++j)
            s = fmaf(base[j * H1 + c], a[j], s);
    }
    __nv_bfloat16 h = __float2bfloat16(s);
    effh[(size_t)bk * 256 + c] = h;
    effl[(size_t)bk * 256 + c] = __float2bfloat16(s - __bfloat162float(h));
}

extern "C" void kernel_launch(void* const* d_in, const int* in_sizes, int n_in,
                              void* d_out, int out_size)
{
    const float* x      = (const float*)d_in[0];
    const float* state  = (const float*)d_in[1];
    const float* enc_W  = (const float*)d_in[2];
    const float* enc_b  = (const float*)d_in[3];
    const float* enc_g  = (const float*)d_in[4];
    const float* enc_bt = (const float*)d_in[5];
    const float* core_W = (const float*)d_in[6];
    const float* core_b = (const float*)d_in[7];
    const float* core_g = (const float*)d_in[8];
    const float* core_bt= (const float*)d_in[9];
    const float* ctx_W  = (const float*)d_in[10];
    const float* ctx_b  = (const float*)d_in[11];
    const float* ctx_g  = (const float*)d_in[12];
    const float* ctx_bt = (const float*)d_in[13];
    const float* att_W1 = (const float*)d_in[14];
    const float* att_b1 = (const float*)d_in[15];
    const float* att_g  = (const float*)d_in[16];
    const float* att_bt = (const float*)d_in[17];
    const float* att_W2 = (const float*)d_in[18];
    const float* att_b2 = (const float*)d_in[19];
    const float* out_W  = (const float*)d_in[20];
    const float* out_b  = (const float*)d_in[21];
    float* out = (float*)d_out;

    float *p_F, *p_G, *p_ctx, *p_att, *p_zero;
    cudaGetSymbolAddress((void**)&p_F,    g_F);
    cudaGetSymbolAddress((void**)&p_G,    g_G);
    cudaGetSymbolAddress((void**)&p_ctx,  g_ctx);
    cudaGetSymbolAddress((void**)&p_att,  g_att);
    cudaGetSymbolAddress((void**)&p_zero, g_zeros);

    __nv_bfloat16 *stah, *stal, *xh, *xl, *s1h, *s1l, *coh, *col_, *efh, *efl;
    cudaGetSymbolAddress((void**)&stah, g_sta_h); cudaGetSymbolAddress((void**)&stal, g_sta_l);
    cudaGetSymbolAddress((void**)&xh,   g_x_h);   cudaGetSymbolAddress((void**)&xl,   g_x_l);
    cudaGetSymbolAddress((void**)&s1h,  g_s1_h);  cudaGetSymbolAddress((void**)&s1l,  g_s1_l);
    cudaGetSymbolAddress((void**)&coh,  g_co_h);  cudaGetSymbolAddress((void**)&col_, g_co_l);
    cudaGetSymbolAddress((void**)&efh,  g_ef_h);  cudaGetSymbolAddress((void**)&efl,  g_ef_l);

    __nv_bfloat16 *ench, *encl, *toph, *topl, *both, *botl,
                  *ctxh, *ctxl, *atth, *attl, *outh, *outl;
    cudaGetSymbolAddress((void**)&ench, g_enc_h);  cudaGetSymbolAddress((void**)&encl, g_enc_l);
    cudaGetSymbolAddress((void**)&toph, g_wtop_h); cudaGetSymbolAddress((void**)&topl, g_wtop_l);
    cudaGetSymbolAddress((void**)&both, g_wbot_h); cudaGetSymbolAddress((void**)&botl, g_wbot_l);
    cudaGetSymbolAddress((void**)&ctxh, g_ctx_h);  cudaGetSymbolAddress((void**)&ctxl, g_ctx_l);
    cudaGetSymbolAddress((void**)&atth, g_att_h);  cudaGetSymbolAddress((void**)&attl, g_att_l);
    cudaGetSymbolAddress((void**)&outh, g_out_h);  cudaGetSymbolAddress((void**)&outl, g_out_l);

    constexpr int SM256 = 2 * (2 * 128 * 72 * 2 + 2 * 64 * 264 * 2) + 1024;  // 209920
    constexpr int SM128 = 2 * (2 * 128 * 72 * 2 + 2 * 64 * 136 * 2) + 1024;  // 144384
    cudaFuncSetAttribute(tc_gemm<256, 250, 256,  0, 0, true,  1, false>,
                         cudaFuncAttributeMaxDynamicSharedMemorySize, SM256);
    cudaFuncSetAttribute(tc_gemm<256, 250, 256,  0, 2, false, 0, true>,
                         cudaFuncAttributeMaxDynamicSharedMemorySize, SM256);
    cudaFuncSetAttribute(tc_gemm<256, 250, 256,  0, 0, true,  0, false>,
                         cudaFuncAttributeMaxDynamicSharedMemorySize, SM256);
    cudaFuncSetAttribute(tc_gemm<128, 100, 256,  0, 1, true,  2, false>,
                         cudaFuncAttributeMaxDynamicSharedMemorySize, SM128);
    cudaFuncSetAttribute(tc_gemm<256, 250, 1088, 2, 2, false, 0, false>,
                         cudaFuncAttributeMaxDynamicSharedMemorySize, SM256);

    // #1: all weight prep
    prep_w_all<<<(573440 + 255) / 256, 256>>>(
        enc_W, core_W, ctx_W, att_W1, out_W,
        ench, encl, toph, topl, both, botl, ctxh, ctxl, atth, attl, outh, outl);

    // #2: activation prep (state + x)
    prep_act<<<(BK * 256 + BK * 576 + 255) / 256, 256>>>(state, x, stah, stal, xh, xl);

    // #3: s1 = LN(relu(state @ enc_W + b)) -> bf16 hi/lo
    tc_gemm<256, 250, 256, 0, 0, true, 1, false><<<BK / 128, 256, SM256>>>(
        stah, stal, nullptr, nullptr, nullptr, nullptr, ench, encl, nullptr, nullptr,
        enc_b, enc_g, enc_bt, nullptr, nullptr, nullptr, nullptr, s1h, s1l, 0);

    // #4: F = s1 @ W_top AND G = s1 @ W_bot (dual-B, one launch)
    tc_gemm<256, 250, 256, 0, 2, false, 0, true><<<2 * (BK / 128), 256, SM256>>>(
        s1h, s1l, nullptr, nullptr, nullptr, nullptr, toph, topl, both, botl,
        p_zero, nullptr, nullptr, nullptr, nullptr, p_F, p_G, nullptr, nullptr, 256);

    // #5: core = LN(relu(F[b,i] + G[b,j] + b)) -> bf16 hi/lo
    combine_kernel<<<RR / 8, 256>>>(p_F, p_G, core_b, core_g, core_bt, coh, col_);

    // #6 (ncu capture window): ctx = LN(relu(core @ ctx_W + b)) -> fp32
    tc_gemm<256, 250, 256, 0, 0, true, 0, false><<<RR / 128, 256, SM256>>>(
        coh, col_, nullptr, nullptr, nullptr, nullptr, ctxh, ctxl, nullptr, nullptr,
        ctx_b, ctx_g, ctx_bt, nullptr, nullptr, p_ctx, nullptr, nullptr, nullptr, H1);

    // #7: att = sigmoid(LN(tanh(core @ att_W1 + b1)) @ att_W2 + b2)
    tc_gemm<128, 100, 256, 0, 1, true, 2, false><<<RR / 128, 256, SM128>>>(
        coh, col_, nullptr, nullptr, nullptr, nullptr, atth, attl, nullptr, nullptr,
        att_b1, att_g, att_bt, att_W2, att_b2, p_att, nullptr, nullptr, nullptr, 0);

    // #8: eff = 7-way attention-weighted reduction of ctx -> bf16 hi/lo
    effect_kernel<<<BK, 256>>>(p_ctx, p_att, efh, efl);

    // #9: out = concat(s1, eff, x) @ out_W + out_b -> fp32 d_out
    tc_gemm<256, 250, 1088, 2, 2, false, 0, false><<<BK / 128, 256, SM256>>>(
        s1h, s1l, efh, efl, xh, xl, outh, outl, nullptr, nullptr,
        out_b, nullptr, nullptr, nullptr, nullptr, out, nullptr, nullptr, nullptr, H1);
}